// round 2
// baseline (speedup 1.0000x reference)
#include <cuda_runtime.h>

// Problem constants (registry shapes are fixed)
#define N_NODES 100000
#define F_XD    64
#define F_UD    128
#define F_OUTD  128
#define B_GLOB  512

// Scratch (no cudaMalloc allowed)
__device__ float g_agg[N_NODES * F_XD];       // 25.6 MB
__device__ float g_U[B_GLOB * 256];           // U_K | U_Q per batch row
__device__ int   g_is64;                      // index dtype flag

// ---------------------------------------------------------------------------
// Kernel 0: probe index dtype. JAX default x64-disabled => int32 likely, but
// the reference *requests* int64. Sample 64 strided int64 interpretations;
// all-in-range [0,N) only happens for genuine int64 data.
// ---------------------------------------------------------------------------
__global__ void probe_kernel(const void* __restrict__ ei, int E, int N) {
    if (threadIdx.x == 0 && blockIdx.x == 0) {
        const long long* p = (const long long*)ei;
        long long stride = (2LL * E) / 64;
        int ok = 1;
        for (int i = 0; i < 64; i++) {
            long long v = p[(long long)i * stride];
            if (v < 0 || v >= N) { ok = 0; break; }
        }
        g_is64 = ok;
    }
}

// ---------------------------------------------------------------------------
// Kernel 1: zero the aggregation buffer (graph replays require re-zeroing)
// ---------------------------------------------------------------------------
__global__ void zero_agg_kernel(int n4) {
    int i = blockIdx.x * blockDim.x + threadIdx.x;
    float4 z = make_float4(0.f, 0.f, 0.f, 0.f);
    if (i < n4) reinterpret_cast<float4*>(g_agg)[i] = z;
}

// ---------------------------------------------------------------------------
// Kernel 2: edge scatter.  agg[dest] += edge_attr[e] * x[src]
// One half-warp (16 lanes) per edge, each lane covers 4 floats (float4),
// accumulated with a single red.global.add.v4.f32 (16B L2 reduction).
// ---------------------------------------------------------------------------
__global__ void scatter_kernel(const void*  __restrict__ ei,
                               const float* __restrict__ attr,
                               const float* __restrict__ x,
                               int E) {
    const int is64 = g_is64;
    const long long* p64 = (const long long*)ei;
    const int*       p32 = (const int*)ei;

    int t      = blockIdx.x * blockDim.x + threadIdx.x;
    int lane   = t & 15;
    int hw     = t >> 4;
    int stride = (gridDim.x * blockDim.x) >> 4;

    for (int e = hw; e < E; e += stride) {
        int s, d;
        if (is64) { s = (int)p64[e]; d = (int)p64[E + e]; }
        else      { s = p32[e];      d = p32[E + e]; }
        float w = attr[e];

        float4 v = *reinterpret_cast<const float4*>(x + (size_t)s * F_XD + lane * 4);
        v.x *= w; v.y *= w; v.z *= w; v.w *= w;

        float* dp = g_agg + (size_t)d * F_XD + lane * 4;
        asm volatile("red.global.add.v4.f32 [%0], {%1, %2, %3, %4};"
                     :: "l"(dp), "f"(v.x), "f"(v.y), "f"(v.z), "f"(v.w)
                     : "memory");
    }
}

// ---------------------------------------------------------------------------
// Kernel 3: precompute  U[b, 0:128]  = u[b] @ W_K[64:192] + b_K
//                       U[b, 128:256]= u[b] @ W_Q[64:192] + b_Q
// ---------------------------------------------------------------------------
__global__ void u_proj_kernel(const float* __restrict__ u,
                              const float* __restrict__ WK, const float* __restrict__ bK,
                              const float* __restrict__ WQ, const float* __restrict__ bQ) {
    __shared__ float su[F_UD];
    int b = blockIdx.x;
    int j = threadIdx.x;                 // 0..255
    if (j < F_UD) su[j] = u[b * F_UD + j];
    __syncthreads();

    const float* W   = (j < F_OUTD) ? WK : WQ;
    int          col = j & (F_OUTD - 1);
    float acc = (j < F_OUTD) ? bK[col] : bQ[col];
#pragma unroll 8
    for (int i = 0; i < F_UD; i++)
        acc = fmaf(su[i], W[(F_XD + i) * F_OUTD + col], acc);
    g_U[b * 256 + j] = acc;
}

// ---------------------------------------------------------------------------
// Kernel 4: fused projection.
//   out_K[n] = agg[n] @ W_K[0:64] + U[batch[n], 0:128]
//   out_Q[n] = agg[n] @ W_Q[0:64] + U[batch[n], 128:256]
// Block tile: 32 nodes x 256 cols.  Thread tile: 8 nodes x 4 cols,
// packed f32x2 FMAs across node pairs.
// ---------------------------------------------------------------------------
#define AS 34   // sA row stride (even -> 8B-aligned pairs)

__device__ __forceinline__ unsigned long long pack2(float a, float b) {
    unsigned long long r;
    asm("mov.b64 %0, {%1, %2};" : "=l"(r) : "f"(a), "f"(b));
    return r;
}
__device__ __forceinline__ void ffma2(unsigned long long& d,
                                      unsigned long long a, unsigned long long b) {
    asm("fma.rn.f32x2 %0, %1, %2, %0;" : "+l"(d) : "l"(a), "l"(b));
}

__global__ void __launch_bounds__(256)
proj_kernel(const void* __restrict__ batch,
            const float* __restrict__ WK,
            const float* __restrict__ WQ,
            float* __restrict__ out, int N) {
    extern __shared__ float sh[];
    float* sW = sh;               // [64][256]
    float* sA = sh + 64 * 256;    // [64][AS] transposed agg tile
    __shared__ int sB[32];

    int tid   = threadIdx.x;
    int node0 = blockIdx.x * 32;

    // Stage W (rows 0..63 of W_K | W_Q): 4096 float4, 16 per thread
    for (int i = tid; i < 64 * 64; i += 256) {
        int k = i >> 6;
        int j = (i & 63) * 4;
        float4 v;
        if (j < 128) v = *reinterpret_cast<const float4*>(WK + k * 128 + j);
        else         v = *reinterpret_cast<const float4*>(WQ + k * 128 + (j - 128));
        *reinterpret_cast<float4*>(sW + k * 256 + j) = v;
    }
    // Stage agg tile transposed: sA[k][n]
    for (int i = tid; i < 32 * 64; i += 256) {
        int n = i >> 6;
        int k = i & 63;
        int gn = node0 + n;
        sA[k * AS + n] = (gn < N) ? g_agg[(size_t)gn * F_XD + k] : 0.f;
    }
    if (tid < 32) {
        int gn = node0 + tid;
        int b = 0;
        if (gn < N) {
            if (g_is64) b = (int)((const long long*)batch)[gn];
            else        b = ((const int*)batch)[gn];
        }
        sB[tid] = b;
    }
    __syncthreads();

    int cg = tid & 63;     // column group -> 4 cols
    int ng = tid >> 6;     // node group   -> 8 nodes
    int c0 = cg * 4;
    int n0 = ng * 8;

    unsigned long long acc[4][4];
#pragma unroll
    for (int p = 0; p < 4; p++)
#pragma unroll
        for (int c = 0; c < 4; c++) acc[p][c] = 0ull;

#pragma unroll 4
    for (int k = 0; k < 64; k++) {
        float4 w = *reinterpret_cast<const float4*>(sW + k * 256 + c0);
        unsigned long long w2[4] = { pack2(w.x, w.x), pack2(w.y, w.y),
                                     pack2(w.z, w.z), pack2(w.w, w.w) };
        const float* ar = sA + k * AS + n0;
        unsigned long long a0 = *reinterpret_cast<const unsigned long long*>(ar + 0);
        unsigned long long a1 = *reinterpret_cast<const unsigned long long*>(ar + 2);
        unsigned long long a2 = *reinterpret_cast<const unsigned long long*>(ar + 4);
        unsigned long long a3 = *reinterpret_cast<const unsigned long long*>(ar + 6);
#pragma unroll
        for (int c = 0; c < 4; c++) {
            ffma2(acc[0][c], a0, w2[c]);
            ffma2(acc[1][c], a1, w2[c]);
            ffma2(acc[2][c], a2, w2[c]);
            ffma2(acc[3][c], a3, w2[c]);
        }
    }

    float* outK = out;
    float* outQ = out + (size_t)N * 128;

#pragma unroll
    for (int p = 0; p < 4; p++) {
        int nA = n0 + 2 * p, nB = nA + 1;
        int gA = node0 + nA, gB = node0 + nB;
        float4 uA = *reinterpret_cast<const float4*>(g_U + sB[nA] * 256 + c0);
        float4 uB = *reinterpret_cast<const float4*>(g_U + sB[nB] * 256 + c0);

        float2 f0 = *reinterpret_cast<float2*>(&acc[p][0]);
        float2 f1 = *reinterpret_cast<float2*>(&acc[p][1]);
        float2 f2 = *reinterpret_cast<float2*>(&acc[p][2]);
        float2 f3 = *reinterpret_cast<float2*>(&acc[p][3]);

        float4 wa = make_float4(f0.x + uA.x, f1.x + uA.y, f2.x + uA.z, f3.x + uA.w);
        float4 wb = make_float4(f0.y + uB.x, f1.y + uB.y, f2.y + uB.z, f3.y + uB.w);

        if (c0 < 128) {
            if (gA < N) *reinterpret_cast<float4*>(outK + (size_t)gA * 128 + c0) = wa;
            if (gB < N) *reinterpret_cast<float4*>(outK + (size_t)gB * 128 + c0) = wb;
        } else {
            if (gA < N) *reinterpret_cast<float4*>(outQ + (size_t)gA * 128 + (c0 - 128)) = wa;
            if (gB < N) *reinterpret_cast<float4*>(outQ + (size_t)gB * 128 + (c0 - 128)) = wb;
        }
    }
}

// ---------------------------------------------------------------------------
extern "C" void kernel_launch(void* const* d_in, const int* in_sizes, int n_in,
                              void* d_out, int out_size) {
    const float* x     = (const float*)d_in[0];
    const void*  ei    = d_in[1];
    const float* attr  = (const float*)d_in[2];
    const float* u     = (const float*)d_in[3];
    const void*  batch = d_in[4];
    const float* WK    = (const float*)d_in[5];
    const float* bK    = (const float*)d_in[6];
    const float* WQ    = (const float*)d_in[7];
    const float* bQ    = (const float*)d_in[8];
    float*       out   = (float*)d_out;

    int E = in_sizes[2];          // edge_attr element count
    int N = in_sizes[4];          // batch element count (= #nodes)

    // 0. dtype probe
    probe_kernel<<<1, 32>>>(ei, E, N);

    // 1. zero agg
    int n4 = (N * F_XD) / 4;
    zero_agg_kernel<<<(n4 + 255) / 256, 256>>>(n4);

    // 2. edge scatter
    scatter_kernel<<<148 * 32, 256>>>(ei, attr, x, E);

    // 3. tiny u-projection
    u_proj_kernel<<<B_GLOB, 256>>>(u, WK, bK, WQ, bQ);

    // 4. fused node projection
    int smem = (64 * 256 + 64 * AS) * (int)sizeof(float);
    cudaFuncSetAttribute(proj_kernel, cudaFuncAttributeMaxDynamicSharedMemorySize, smem);
    proj_kernel<<<(N + 31) / 32, 256, smem>>>(batch, WK, WQ, out, N);
}

// round 3
// speedup vs baseline: 1.0149x; 1.0149x over previous
#include <cuda_runtime.h>

// Problem constants (registry shapes are fixed)
#define N_NODES 100000
#define E_MAX   3200000
#define F_XD    64
#define F_UD    128
#define F_OUTD  128
#define B_GLOB  512
#define SCAN_B  1024   // elements per scan block

// Scratch (no cudaMalloc allowed)
__device__ float g_agg[N_NODES * F_XD];       // 25.6 MB
__device__ float g_U[B_GLOB * 256];           // U_K | U_Q per batch row
__device__ int   g_is64;                      // index dtype flag
__device__ int   g_deg[N_NODES];              // in-degree per dest
__device__ int   g_rowptr[N_NODES];           // CSR row starts (exclusive scan)
__device__ int   g_cursor[N_NODES];           // fill cursors
__device__ int   g_bsum[128];                 // scan block sums
__device__ int   g_boff[128];                 // scan block offsets
__device__ uint2 g_edges[E_MAX];              // bucketed {src, attr_bits}

// ---------------------------------------------------------------------------
// Kernel 0: probe index dtype (int64 as declared vs int32 from JAX x64-off).
// ---------------------------------------------------------------------------
__global__ void probe_kernel(const void* __restrict__ ei, int E, int N) {
    if (threadIdx.x == 0 && blockIdx.x == 0) {
        const long long* p = (const long long*)ei;
        long long stride = (2LL * E) / 64;
        int ok = 1;
        for (int i = 0; i < 64; i++) {
            long long v = p[(long long)i * stride];
            if (v < 0 || v >= N) { ok = 0; break; }
        }
        g_is64 = ok;
    }
}

// ---------------------------------------------------------------------------
// CSR build
// ---------------------------------------------------------------------------
__global__ void zero_deg_kernel(int N) {
    int i = blockIdx.x * blockDim.x + threadIdx.x;
    if (i < N) g_deg[i] = 0;
}

__global__ void hist_kernel(const void* __restrict__ ei, int E) {
    const int is64 = g_is64;
    int e = blockIdx.x * blockDim.x + threadIdx.x;
    if (e >= E) return;
    int d = is64 ? (int)((const long long*)ei)[E + e] : ((const int*)ei)[E + e];
    atomicAdd(&g_deg[d], 1);
}

__global__ void scan1_kernel(int N) {                 // per-block sums
    __shared__ int ss[256];
    int b = blockIdx.x, t = threadIdx.x;
    int base = b * SCAN_B + t * 4;
    int s = 0;
#pragma unroll
    for (int j = 0; j < 4; j++) {
        int idx = base + j;
        if (idx < N) s += g_deg[idx];
    }
    ss[t] = s;
    __syncthreads();
    for (int off = 128; off > 0; off >>= 1) {
        if (t < off) ss[t] += ss[t + off];
        __syncthreads();
    }
    if (t == 0) g_bsum[b] = ss[0];
}

__global__ void scan2_kernel(int nblk) {              // serial scan of ~98 sums
    if (threadIdx.x == 0) {
        int acc = 0;
        for (int i = 0; i < nblk; i++) { g_boff[i] = acc; acc += g_bsum[i]; }
    }
}

__global__ void scan3_kernel(int N) {                 // final exclusive scan
    __shared__ int ss[256];
    int b = blockIdx.x, t = threadIdx.x;
    int base = b * SCAN_B + t * 4;
    int v[4]; int tsum = 0;
#pragma unroll
    for (int j = 0; j < 4; j++) {
        int idx = base + j;
        v[j] = (idx < N) ? g_deg[idx] : 0;
        tsum += v[j];
    }
    ss[t] = tsum;
    __syncthreads();
    // Hillis-Steele inclusive scan of 256 thread totals
    for (int off = 1; off < 256; off <<= 1) {
        int add = (t >= off) ? ss[t - off] : 0;
        __syncthreads();
        ss[t] += add;
        __syncthreads();
    }
    int run = g_boff[b] + ss[t] - tsum;   // exclusive prefix for this thread
#pragma unroll
    for (int j = 0; j < 4; j++) {
        int idx = base + j;
        if (idx < N) { g_rowptr[idx] = run; g_cursor[idx] = run; }
        run += v[j];
    }
}

__global__ void fill_kernel(const void*  __restrict__ ei,
                            const float* __restrict__ attr, int E) {
    const int is64 = g_is64;
    int e = blockIdx.x * blockDim.x + threadIdx.x;
    if (e >= E) return;
    int s, d;
    if (is64) { s = (int)((const long long*)ei)[e]; d = (int)((const long long*)ei)[E + e]; }
    else      { s = ((const int*)ei)[e];            d = ((const int*)ei)[E + e]; }
    int pos = atomicAdd(&g_cursor[d], 1);
    g_edges[pos] = make_uint2((unsigned)s, __float_as_uint(attr[e]));
}

// ---------------------------------------------------------------------------
// Aggregate: one half-warp (16 lanes) per dest node; lane owns 4 cols.
// agg[d] = sum_{e in in(d)} attr_e * x[src_e]     (single store per dest)
// ---------------------------------------------------------------------------
__global__ void agg_kernel(const float* __restrict__ x, int N) {
    int t    = blockIdx.x * blockDim.x + threadIdx.x;
    int lane = t & 15;
    int d    = t >> 4;
    if (d >= N) return;

    int start = g_rowptr[d];
    int deg   = g_deg[d];

    float4 acc0 = make_float4(0.f, 0.f, 0.f, 0.f);
    float4 acc1 = make_float4(0.f, 0.f, 0.f, 0.f);

    int i = 0;
    for (; i + 1 < deg; i += 2) {
        uint2 e0 = g_edges[start + i];
        uint2 e1 = g_edges[start + i + 1];
        float4 v0 = *reinterpret_cast<const float4*>(x + (size_t)e0.x * F_XD + lane * 4);
        float4 v1 = *reinterpret_cast<const float4*>(x + (size_t)e1.x * F_XD + lane * 4);
        float w0 = __uint_as_float(e0.y);
        float w1 = __uint_as_float(e1.y);
        acc0.x = fmaf(w0, v0.x, acc0.x); acc0.y = fmaf(w0, v0.y, acc0.y);
        acc0.z = fmaf(w0, v0.z, acc0.z); acc0.w = fmaf(w0, v0.w, acc0.w);
        acc1.x = fmaf(w1, v1.x, acc1.x); acc1.y = fmaf(w1, v1.y, acc1.y);
        acc1.z = fmaf(w1, v1.z, acc1.z); acc1.w = fmaf(w1, v1.w, acc1.w);
    }
    if (i < deg) {
        uint2 e0 = g_edges[start + i];
        float4 v0 = *reinterpret_cast<const float4*>(x + (size_t)e0.x * F_XD + lane * 4);
        float w0 = __uint_as_float(e0.y);
        acc0.x = fmaf(w0, v0.x, acc0.x); acc0.y = fmaf(w0, v0.y, acc0.y);
        acc0.z = fmaf(w0, v0.z, acc0.z); acc0.w = fmaf(w0, v0.w, acc0.w);
    }
    acc0.x += acc1.x; acc0.y += acc1.y; acc0.z += acc1.z; acc0.w += acc1.w;
    *reinterpret_cast<float4*>(g_agg + (size_t)d * F_XD + lane * 4) = acc0;
}

// ---------------------------------------------------------------------------
// Kernel 3: precompute  U[b, 0:128]  = u[b] @ W_K[64:192] + b_K
//                       U[b, 128:256]= u[b] @ W_Q[64:192] + b_Q
// ---------------------------------------------------------------------------
__global__ void u_proj_kernel(const float* __restrict__ u,
                              const float* __restrict__ WK, const float* __restrict__ bK,
                              const float* __restrict__ WQ, const float* __restrict__ bQ) {
    __shared__ float su[F_UD];
    int b = blockIdx.x;
    int j = threadIdx.x;                 // 0..255
    if (j < F_UD) su[j] = u[b * F_UD + j];
    __syncthreads();

    const float* W   = (j < F_OUTD) ? WK : WQ;
    int          col = j & (F_OUTD - 1);
    float acc = (j < F_OUTD) ? bK[col] : bQ[col];
#pragma unroll 8
    for (int i = 0; i < F_UD; i++)
        acc = fmaf(su[i], W[(F_XD + i) * F_OUTD + col], acc);
    g_U[b * 256 + j] = acc;
}

// ---------------------------------------------------------------------------
// Kernel 4: fused projection (unchanged from R2 — passed correctness).
// ---------------------------------------------------------------------------
#define AS 34

__device__ __forceinline__ unsigned long long pack2(float a, float b) {
    unsigned long long r;
    asm("mov.b64 %0, {%1, %2};" : "=l"(r) : "f"(a), "f"(b));
    return r;
}
__device__ __forceinline__ void ffma2(unsigned long long& d,
                                      unsigned long long a, unsigned long long b) {
    asm("fma.rn.f32x2 %0, %1, %2, %0;" : "+l"(d) : "l"(a), "l"(b));
}

__global__ void __launch_bounds__(256)
proj_kernel(const void* __restrict__ batch,
            const float* __restrict__ WK,
            const float* __restrict__ WQ,
            float* __restrict__ out, int N) {
    extern __shared__ float sh[];
    float* sW = sh;               // [64][256]
    float* sA = sh + 64 * 256;    // [64][AS]
    __shared__ int sB[32];

    int tid   = threadIdx.x;
    int node0 = blockIdx.x * 32;

    for (int i = tid; i < 64 * 64; i += 256) {
        int k = i >> 6;
        int j = (i & 63) * 4;
        float4 v;
        if (j < 128) v = *reinterpret_cast<const float4*>(WK + k * 128 + j);
        else         v = *reinterpret_cast<const float4*>(WQ + k * 128 + (j - 128));
        *reinterpret_cast<float4*>(sW + k * 256 + j) = v;
    }
    for (int i = tid; i < 32 * 64; i += 256) {
        int n = i >> 6;
        int k = i & 63;
        int gn = node0 + n;
        sA[k * AS + n] = (gn < N) ? g_agg[(size_t)gn * F_XD + k] : 0.f;
    }
    if (tid < 32) {
        int gn = node0 + tid;
        int b = 0;
        if (gn < N) {
            if (g_is64) b = (int)((const long long*)batch)[gn];
            else        b = ((const int*)batch)[gn];
        }
        sB[tid] = b;
    }
    __syncthreads();

    int cg = tid & 63;
    int ng = tid >> 6;
    int c0 = cg * 4;
    int n0 = ng * 8;

    unsigned long long acc[4][4];
#pragma unroll
    for (int p = 0; p < 4; p++)
#pragma unroll
        for (int c = 0; c < 4; c++) acc[p][c] = 0ull;

#pragma unroll 4
    for (int k = 0; k < 64; k++) {
        float4 w = *reinterpret_cast<const float4*>(sW + k * 256 + c0);
        unsigned long long w2[4] = { pack2(w.x, w.x), pack2(w.y, w.y),
                                     pack2(w.z, w.z), pack2(w.w, w.w) };
        const float* ar = sA + k * AS + n0;
        unsigned long long a0 = *reinterpret_cast<const unsigned long long*>(ar + 0);
        unsigned long long a1 = *reinterpret_cast<const unsigned long long*>(ar + 2);
        unsigned long long a2 = *reinterpret_cast<const unsigned long long*>(ar + 4);
        unsigned long long a3 = *reinterpret_cast<const unsigned long long*>(ar + 6);
#pragma unroll
        for (int c = 0; c < 4; c++) {
            ffma2(acc[0][c], a0, w2[c]);
            ffma2(acc[1][c], a1, w2[c]);
            ffma2(acc[2][c], a2, w2[c]);
            ffma2(acc[3][c], a3, w2[c]);
        }
    }

    float* outK = out;
    float* outQ = out + (size_t)N * 128;

#pragma unroll
    for (int p = 0; p < 4; p++) {
        int nA = n0 + 2 * p, nB = nA + 1;
        int gA = node0 + nA, gB = node0 + nB;
        float4 uA = *reinterpret_cast<const float4*>(g_U + sB[nA] * 256 + c0);
        float4 uB = *reinterpret_cast<const float4*>(g_U + sB[nB] * 256 + c0);

        float2 f0 = *reinterpret_cast<float2*>(&acc[p][0]);
        float2 f1 = *reinterpret_cast<float2*>(&acc[p][1]);
        float2 f2 = *reinterpret_cast<float2*>(&acc[p][2]);
        float2 f3 = *reinterpret_cast<float2*>(&acc[p][3]);

        float4 wa = make_float4(f0.x + uA.x, f1.x + uA.y, f2.x + uA.z, f3.x + uA.w);
        float4 wb = make_float4(f0.y + uB.x, f1.y + uB.y, f2.y + uB.z, f3.y + uB.w);

        if (c0 < 128) {
            if (gA < N) *reinterpret_cast<float4*>(outK + (size_t)gA * 128 + c0) = wa;
            if (gB < N) *reinterpret_cast<float4*>(outK + (size_t)gB * 128 + c0) = wb;
        } else {
            if (gA < N) *reinterpret_cast<float4*>(outQ + (size_t)gA * 128 + (c0 - 128)) = wa;
            if (gB < N) *reinterpret_cast<float4*>(outQ + (size_t)gB * 128 + (c0 - 128)) = wb;
        }
    }
}

// ---------------------------------------------------------------------------
extern "C" void kernel_launch(void* const* d_in, const int* in_sizes, int n_in,
                              void* d_out, int out_size) {
    const float* x     = (const float*)d_in[0];
    const void*  ei    = d_in[1];
    const float* attr  = (const float*)d_in[2];
    const float* u     = (const float*)d_in[3];
    const void*  batch = d_in[4];
    const float* WK    = (const float*)d_in[5];
    const float* bK    = (const float*)d_in[6];
    const float* WQ    = (const float*)d_in[7];
    const float* bQ    = (const float*)d_in[8];
    float*       out   = (float*)d_out;

    int E = in_sizes[2];
    int N = in_sizes[4];
    int nblk = (N + SCAN_B - 1) / SCAN_B;

    probe_kernel<<<1, 32>>>(ei, E, N);
    zero_deg_kernel<<<(N + 255) / 256, 256>>>(N);
    hist_kernel<<<(E + 255) / 256, 256>>>(ei, E);
    scan1_kernel<<<nblk, 256>>>(N);
    scan2_kernel<<<1, 32>>>(nblk);
    scan3_kernel<<<nblk, 256>>>(N);
    fill_kernel<<<(E + 255) / 256, 256>>>(ei, attr, E);
    agg_kernel<<<(N * 16 + 255) / 256, 256>>>(x, N);

    u_proj_kernel<<<B_GLOB, 256>>>(u, WK, bK, WQ, bQ);

    int smem = (64 * 256 + 64 * AS) * (int)sizeof(float);
    cudaFuncSetAttribute(proj_kernel, cudaFuncAttributeMaxDynamicSharedMemorySize, smem);
    proj_kernel<<<(N + 31) / 32, 256, smem>>>(batch, WK, WQ, out, N);
}

// round 4
// speedup vs baseline: 1.0470x; 1.0317x over previous
#include <cuda_runtime.h>

#define N_NODES 100000
#define E_MAX   3200000
#define F_XD    64
#define F_UD    128
#define F_OUTD  128
#define B_GLOB  512
#define SCAN_B  1024

typedef unsigned long long ull;

__device__ float g_agg[N_NODES * F_XD];
__device__ float g_U[B_GLOB * 256];
__device__ int   g_is64;
__device__ int   g_deg[N_NODES];
__device__ int   g_rowptr[N_NODES];
__device__ int   g_cursor[N_NODES];
__device__ int   g_bsum[128];
__device__ int   g_boff[128];
__device__ uint2 g_edges[E_MAX];

__device__ __forceinline__ ull pack2(float a, float b) {
    ull r; asm("mov.b64 %0, {%1, %2};" : "=l"(r) : "f"(a), "f"(b)); return r;
}
__device__ __forceinline__ void ffma2(ull& d, ull a, ull b) {
    asm("fma.rn.f32x2 %0, %1, %2, %0;" : "+l"(d) : "l"(a), "l"(b));
}
__device__ __forceinline__ ull add2(ull a, ull b) {
    ull r; asm("add.rn.f32x2 %0, %1, %2;" : "=l"(r) : "l"(a), "l"(b)); return r;
}

// ---------------------------------------------------------------------------
// Kernel 1: zero degree counters + (thread 0) index-dtype probe.
// ---------------------------------------------------------------------------
__global__ void zero_probe_kernel(const void* __restrict__ ei, int E, int N) {
    int i = blockIdx.x * blockDim.x + threadIdx.x;
    if (i < N) g_deg[i] = 0;
    if (i == 0) {
        const long long* p = (const long long*)ei;
        long long stride = (2LL * E) / 64;
        int ok = 1;
        for (int j = 0; j < 64; j++) {
            long long v = p[(long long)j * stride];
            if (v < 0 || v >= N) { ok = 0; break; }
        }
        g_is64 = ok;
    }
}

// ---------------------------------------------------------------------------
// Kernel 2: in-degree histogram (vectorized int4 on int32 path).
// ---------------------------------------------------------------------------
__global__ void hist_kernel(const void* __restrict__ ei, int E) {
    const int is64 = g_is64;
    int t = blockIdx.x * blockDim.x + threadIdx.x;
    if (!is64 && (E & 3) == 0) {
        int n4 = E >> 2;
        if (t >= n4) return;
        int4 d4 = reinterpret_cast<const int4*>((const int*)ei + E)[t];
        atomicAdd(&g_deg[d4.x], 1);
        atomicAdd(&g_deg[d4.y], 1);
        atomicAdd(&g_deg[d4.z], 1);
        atomicAdd(&g_deg[d4.w], 1);
    } else {
        for (int e = t; e < E; e += gridDim.x * blockDim.x) {
            int d = is64 ? (int)((const long long*)ei)[E + e]
                         : ((const int*)ei)[E + e];
            atomicAdd(&g_deg[d], 1);
        }
    }
}

// ---------------------------------------------------------------------------
// Exclusive scan (3 phases)
// ---------------------------------------------------------------------------
__global__ void scan1_kernel(int N) {
    __shared__ int ss[256];
    int b = blockIdx.x, t = threadIdx.x;
    int base = b * SCAN_B + t * 4;
    int s = 0;
#pragma unroll
    for (int j = 0; j < 4; j++) { int idx = base + j; if (idx < N) s += g_deg[idx]; }
    ss[t] = s;
    __syncthreads();
    for (int off = 128; off > 0; off >>= 1) {
        if (t < off) ss[t] += ss[t + off];
        __syncthreads();
    }
    if (t == 0) g_bsum[b] = ss[0];
}

__global__ void scan2_kernel(int nblk) {
    if (threadIdx.x == 0) {
        int acc = 0;
        for (int i = 0; i < nblk; i++) { g_boff[i] = acc; acc += g_bsum[i]; }
    }
}

__global__ void scan3_kernel(int N) {
    __shared__ int ss[256];
    int b = blockIdx.x, t = threadIdx.x;
    int base = b * SCAN_B + t * 4;
    int v[4]; int tsum = 0;
#pragma unroll
    for (int j = 0; j < 4; j++) {
        int idx = base + j;
        v[j] = (idx < N) ? g_deg[idx] : 0;
        tsum += v[j];
    }
    ss[t] = tsum;
    __syncthreads();
    for (int off = 1; off < 256; off <<= 1) {
        int add = (t >= off) ? ss[t - off] : 0;
        __syncthreads();
        ss[t] += add;
        __syncthreads();
    }
    int run = g_boff[b] + ss[t] - tsum;
#pragma unroll
    for (int j = 0; j < 4; j++) {
        int idx = base + j;
        if (idx < N) { g_rowptr[idx] = run; g_cursor[idx] = run; }
        run += v[j];
    }
}

// ---------------------------------------------------------------------------
// Kernel: bucket edges by dest
// ---------------------------------------------------------------------------
__global__ void fill_kernel(const void*  __restrict__ ei,
                            const float* __restrict__ attr, int E) {
    const int is64 = g_is64;
    int e = blockIdx.x * blockDim.x + threadIdx.x;
    if (e >= E) return;
    int s, d;
    if (is64) { s = (int)((const long long*)ei)[e]; d = (int)((const long long*)ei)[E + e]; }
    else      { s = ((const int*)ei)[e];            d = ((const int*)ei)[E + e]; }
    int pos = atomicAdd(&g_cursor[d], 1);
    g_edges[pos] = make_uint2((unsigned)s, __float_as_uint(attr[e]));
}

// ---------------------------------------------------------------------------
// Aggregate: ONE WARP per dest; lane owns 2 cols (float2 / f32x2).
// 4-edge unroll -> 4 independent accumulators -> MLP=4 on the x gather.
// Also covers zero-init (every row stored exactly once).
// ---------------------------------------------------------------------------
__global__ void __launch_bounds__(256)
agg_kernel(const float* __restrict__ x, int N) {
    int t    = blockIdx.x * blockDim.x + threadIdx.x;
    int lane = t & 31;
    int d    = t >> 5;
    if (d >= N) return;

    int start = g_rowptr[d];
    int deg   = g_deg[d];
    const float* xb = x + lane * 2;

    ull a0 = 0, a1 = 0, a2 = 0, a3 = 0;
    int i = 0;
    for (; i + 4 <= deg; i += 4) {
        uint2 e0 = g_edges[start + i + 0];
        uint2 e1 = g_edges[start + i + 1];
        uint2 e2 = g_edges[start + i + 2];
        uint2 e3 = g_edges[start + i + 3];
        ull v0 = *reinterpret_cast<const ull*>(xb + (size_t)e0.x * F_XD);
        ull v1 = *reinterpret_cast<const ull*>(xb + (size_t)e1.x * F_XD);
        ull v2 = *reinterpret_cast<const ull*>(xb + (size_t)e2.x * F_XD);
        ull v3 = *reinterpret_cast<const ull*>(xb + (size_t)e3.x * F_XD);
        float w0 = __uint_as_float(e0.y), w1 = __uint_as_float(e1.y);
        float w2 = __uint_as_float(e2.y), w3 = __uint_as_float(e3.y);
        ffma2(a0, v0, pack2(w0, w0));
        ffma2(a1, v1, pack2(w1, w1));
        ffma2(a2, v2, pack2(w2, w2));
        ffma2(a3, v3, pack2(w3, w3));
    }
    for (; i < deg; i++) {
        uint2 e0 = g_edges[start + i];
        ull v0 = *reinterpret_cast<const ull*>(xb + (size_t)e0.x * F_XD);
        float w0 = __uint_as_float(e0.y);
        ffma2(a0, v0, pack2(w0, w0));
    }
    ull s = add2(add2(a0, a1), add2(a2, a3));
    *reinterpret_cast<ull*>(g_agg + (size_t)d * F_XD + lane * 2) = s;
}

// ---------------------------------------------------------------------------
// u-projection: 4 batch rows per block, W value reused x4 in registers.
// ---------------------------------------------------------------------------
__global__ void u_proj_kernel(const float* __restrict__ u,
                              const float* __restrict__ WK, const float* __restrict__ bK,
                              const float* __restrict__ WQ, const float* __restrict__ bQ) {
    __shared__ float su[4][F_UD];
    int b0 = blockIdx.x * 4;
    int j  = threadIdx.x;                // 0..255
    for (int i = j; i < 4 * F_UD; i += 256)
        su[i >> 7][i & 127] = u[(b0 + (i >> 7)) * F_UD + (i & 127)];
    __syncthreads();

    const float* W   = (j < F_OUTD) ? WK : WQ;
    int          col = j & (F_OUTD - 1);
    float bias = (j < F_OUTD) ? bK[col] : bQ[col];
    float acc0 = bias, acc1 = bias, acc2 = bias, acc3 = bias;
#pragma unroll 4
    for (int k = 0; k < F_UD; k++) {
        float wv = W[(F_XD + k) * F_OUTD + col];
        acc0 = fmaf(su[0][k], wv, acc0);
        acc1 = fmaf(su[1][k], wv, acc1);
        acc2 = fmaf(su[2][k], wv, acc2);
        acc3 = fmaf(su[3][k], wv, acc3);
    }
    g_U[(b0 + 0) * 256 + j] = acc0;
    g_U[(b0 + 1) * 256 + j] = acc1;
    g_U[(b0 + 2) * 256 + j] = acc2;
    g_U[(b0 + 3) * 256 + j] = acc3;
}

// ---------------------------------------------------------------------------
// Fused projection: 64-node tile, 512 threads, f32x2 FMAs.
// ---------------------------------------------------------------------------
#define AS2 66

__global__ void __launch_bounds__(512)
proj_kernel(const void* __restrict__ batch,
            const float* __restrict__ WK,
            const float* __restrict__ WQ,
            float* __restrict__ out, int N) {
    extern __shared__ float sh[];
    float* sW = sh;                 // [64][256]
    float* sA = sh + 64 * 256;      // [64][AS2]
    __shared__ int sB[64];

    int tid   = threadIdx.x;
    int node0 = blockIdx.x * 64;

    for (int i = tid; i < 64 * 64; i += 512) {
        int k = i >> 6;
        int j = (i & 63) * 4;
        float4 v;
        if (j < 128) v = *reinterpret_cast<const float4*>(WK + k * 128 + j);
        else         v = *reinterpret_cast<const float4*>(WQ + k * 128 + (j - 128));
        *reinterpret_cast<float4*>(sW + k * 256 + j) = v;
    }
    for (int i = tid; i < 64 * 64; i += 512) {
        int n = i >> 6;
        int k = i & 63;
        int gn = node0 + n;
        sA[k * AS2 + n] = (gn < N) ? g_agg[(size_t)gn * F_XD + k] : 0.f;
    }
    if (tid < 64) {
        int gn = node0 + tid;
        int b = 0;
        if (gn < N) {
            if (g_is64) b = (int)((const long long*)batch)[gn];
            else        b = ((const int*)batch)[gn];
        }
        sB[tid] = b;
    }
    __syncthreads();

    int cg = tid & 63;      // 64 col groups x 4 cols
    int ng = tid >> 6;      // 8 node groups x 8 nodes
    int c0 = cg * 4;
    int n0 = ng * 8;

    ull acc[4][4];
#pragma unroll
    for (int p = 0; p < 4; p++)
#pragma unroll
        for (int c = 0; c < 4; c++) acc[p][c] = 0ull;

#pragma unroll 4
    for (int k = 0; k < 64; k++) {
        float4 w = *reinterpret_cast<const float4*>(sW + k * 256 + c0);
        ull w2[4] = { pack2(w.x, w.x), pack2(w.y, w.y),
                      pack2(w.z, w.z), pack2(w.w, w.w) };
        const float* ar = sA + k * AS2 + n0;
        ull a0 = *reinterpret_cast<const ull*>(ar + 0);
        ull a1 = *reinterpret_cast<const ull*>(ar + 2);
        ull a2 = *reinterpret_cast<const ull*>(ar + 4);
        ull a3 = *reinterpret_cast<const ull*>(ar + 6);
#pragma unroll
        for (int c = 0; c < 4; c++) {
            ffma2(acc[0][c], a0, w2[c]);
            ffma2(acc[1][c], a1, w2[c]);
            ffma2(acc[2][c], a2, w2[c]);
            ffma2(acc[3][c], a3, w2[c]);
        }
    }

    float* outK = out;
    float* outQ = out + (size_t)N * 128;

#pragma unroll
    for (int p = 0; p < 4; p++) {
        int nA = n0 + 2 * p, nB = nA + 1;
        int gA = node0 + nA, gB = node0 + nB;
        float4 uA = *reinterpret_cast<const float4*>(g_U + sB[nA] * 256 + c0);
        float4 uB = *reinterpret_cast<const float4*>(g_U + sB[nB] * 256 + c0);

        float2 f0 = *reinterpret_cast<float2*>(&acc[p][0]);
        float2 f1 = *reinterpret_cast<float2*>(&acc[p][1]);
        float2 f2 = *reinterpret_cast<float2*>(&acc[p][2]);
        float2 f3 = *reinterpret_cast<float2*>(&acc[p][3]);

        float4 wa = make_float4(f0.x + uA.x, f1.x + uA.y, f2.x + uA.z, f3.x + uA.w);
        float4 wb = make_float4(f0.y + uB.x, f1.y + uB.y, f2.y + uB.z, f3.y + uB.w);

        if (c0 < 128) {
            if (gA < N) *reinterpret_cast<float4*>(outK + (size_t)gA * 128 + c0) = wa;
            if (gB < N) *reinterpret_cast<float4*>(outK + (size_t)gB * 128 + c0) = wb;
        } else {
            if (gA < N) *reinterpret_cast<float4*>(outQ + (size_t)gA * 128 + (c0 - 128)) = wa;
            if (gB < N) *reinterpret_cast<float4*>(outQ + (size_t)gB * 128 + (c0 - 128)) = wb;
        }
    }
}

// ---------------------------------------------------------------------------
extern "C" void kernel_launch(void* const* d_in, const int* in_sizes, int n_in,
                              void* d_out, int out_size) {
    const float* x     = (const float*)d_in[0];
    const void*  ei    = d_in[1];
    const float* attr  = (const float*)d_in[2];
    const float* u     = (const float*)d_in[3];
    const void*  batch = d_in[4];
    const float* WK    = (const float*)d_in[5];
    const float* bK    = (const float*)d_in[6];
    const float* WQ    = (const float*)d_in[7];
    const float* bQ    = (const float*)d_in[8];
    float*       out   = (float*)d_out;

    int E = in_sizes[2];
    int N = in_sizes[4];
    int nblk = (N + SCAN_B - 1) / SCAN_B;

    zero_probe_kernel<<<(N + 255) / 256, 256>>>(ei, E, N);
    hist_kernel<<<((E >> 2) + 255) / 256, 256>>>(ei, E);
    scan1_kernel<<<nblk, 256>>>(N);
    scan2_kernel<<<1, 32>>>(nblk);
    scan3_kernel<<<nblk, 256>>>(N);
    fill_kernel<<<(E + 255) / 256, 256>>>(ei, attr, E);
    agg_kernel<<<(N * 32 + 255) / 256, 256>>>(x, N);

    u_proj_kernel<<<B_GLOB / 4, 256>>>(u, WK, bK, WQ, bQ);

    int smem = (64 * 256 + 64 * AS2) * (int)sizeof(float);
    cudaFuncSetAttribute(proj_kernel, cudaFuncAttributeMaxDynamicSharedMemorySize, smem);
    proj_kernel<<<(N + 63) / 64, 512, smem>>>(batch, WK, WQ, out, N);
}